// round 1
// baseline (speedup 1.0000x reference)
#include <cuda_runtime.h>

#define DMODEL 1024
#define NHEADS 16
#define DK     64
#define BATCH  4
#define SEQ    2048
#define ROWS   (BATCH*SEQ)    // 8192
#define BH     (BATCH*NHEADS) // 64

// ---------------- scratch (static device arrays; no runtime alloc) ----------------
__device__ float g_q[(size_t)BH*SEQ*DK];
__device__ float g_k[(size_t)BH*SEQ*DK];
__device__ float g_v[(size_t)BH*SEQ*DK];
__device__ float g_ctx[(size_t)ROWS*DMODEL];
__device__ float g_pre[(size_t)ROWS*DMODEL];

// ---------------- GEMM: C = A(ROWSxDMODEL) @ W(DMODELxDMODEL) + bias ----------------
// mode 0: scatter to QKV layout [(b*H+h)*SEQ + s]*DK + d, scaled by `scale`
// mode 1: add residual, write row-major to out
__global__ __launch_bounds__(256) void gemm_kernel(
    const float* __restrict__ A, const float* __restrict__ W,
    const float* __restrict__ bias, const float* __restrict__ resid,
    float* __restrict__ out, int mode, float scale)
{
    __shared__ float As[8][128];
    __shared__ float Bs[8][128];

    const int tid  = threadIdx.x;
    const int tx   = tid & 15;
    const int ty   = tid >> 4;
    const int brow = blockIdx.y * 128;
    const int bcol = blockIdx.x * 128;

    float acc[8][8];
    #pragma unroll
    for (int i = 0; i < 8; i++)
        #pragma unroll
        for (int j = 0; j < 8; j++) acc[i][j] = 0.f;

    const int arow  = tid >> 1;        // 0..127
    const int acol4 = (tid & 1) * 4;   // 0 or 4
    const int wrow  = tid >> 5;        // 0..7
    const int wcol4 = (tid & 31) * 4;  // 0..124

    const float* Aptr = A + (size_t)(brow + arow) * DMODEL + acol4;
    const float* Wptr = W + (size_t)wrow * DMODEL + bcol + wcol4;

    for (int kt = 0; kt < DMODEL; kt += 8) {
        float4 av = *(const float4*)(Aptr + kt);
        As[acol4 + 0][arow] = av.x;
        As[acol4 + 1][arow] = av.y;
        As[acol4 + 2][arow] = av.z;
        As[acol4 + 3][arow] = av.w;
        float4 wv = *(const float4*)(Wptr + (size_t)kt * DMODEL);
        *(float4*)&Bs[wrow][wcol4] = wv;
        __syncthreads();

        #pragma unroll
        for (int kk = 0; kk < 8; kk++) {
            float a[8], b[8];
            #pragma unroll
            for (int i = 0; i < 8; i++) a[i] = As[kk][ty + 16*i];
            #pragma unroll
            for (int j = 0; j < 8; j++) b[j] = Bs[kk][tx + 16*j];
            #pragma unroll
            for (int i = 0; i < 8; i++)
                #pragma unroll
                for (int j = 0; j < 8; j++) acc[i][j] += a[i]*b[j];
        }
        __syncthreads();
    }

    #pragma unroll
    for (int i = 0; i < 8; i++) {
        int row = brow + ty + 16*i;
        #pragma unroll
        for (int j = 0; j < 8; j++) {
            int col = bcol + tx + 16*j;
            float v = acc[i][j] + bias[col];
            if (mode == 0) {
                v *= scale;
                int b = row >> 11, s = row & (SEQ-1);
                int h = col >> 6,  d = col & (DK-1);
                out[(size_t)((b*NHEADS + h)*SEQ + s)*DK + d] = v;
            } else {
                v += resid[(size_t)row*DMODEL + col];
                out[(size_t)row*DMODEL + col] = v;
            }
        }
    }
}

// ---------------- fused attention: scores + mask + softmax + att write + PV ----------------
#define QT   16
#define KT   128
#define KSTR 68   // padded row stride (floats), multiple of 4 for float4 smem access
#define ATTN_SMEM_BYTES ((QT*SEQ + KT*KSTR + QT*KSTR + QT + SEQ) * 4)

__global__ __launch_bounds__(256, 1) void attn_kernel(
    const float* __restrict__ Q, const float* __restrict__ K, const float* __restrict__ V,
    const int* __restrict__ mask, float* __restrict__ ctx, float* __restrict__ attout)
{
    extern __shared__ float sm[];
    float* sc   = sm;                 // QT * SEQ scores
    float* kv   = sc + QT*SEQ;        // KT * KSTR staging for K/V chunks
    float* qs   = kv + KT*KSTR;       // QT * KSTR Q tile
    float* rinv = qs + QT*KSTR;       // QT row 1/sum
    int*   msk  = (int*)(rinv + QT);  // SEQ mask

    const int tid = threadIdx.x;
    const int b   = blockIdx.z, h = blockIdx.y;
    const int bh  = b*NHEADS + h;
    const int q0  = blockIdx.x * QT;
    const float* Qb = Q + (size_t)bh*SEQ*DK;
    const float* Kb = K + (size_t)bh*SEQ*DK;
    const float* Vb = V + (size_t)bh*SEQ*DK;

    for (int i = tid; i < SEQ; i += 256) msk[i] = mask[b*SEQ + i];
    for (int i = tid; i < QT*(DK/4); i += 256) {
        int r = i >> 4, c4 = i & 15;
        float4 v = *(const float4*)(Qb + (size_t)(q0 + r)*DK + c4*4);
        *(float4*)(qs + r*KSTR + c4*4) = v;
    }
    __syncthreads();

    const int tq = tid >> 4, tk = tid & 15;

    // cache this thread's q row in registers (64 floats)
    float4 qr[16];
    #pragma unroll
    for (int c = 0; c < 16; c++) qr[c] = *(const float4*)(qs + tq*KSTR + c*4);

    // ---- QK^T ----
    for (int kc = 0; kc < SEQ; kc += KT) {
        for (int i = tid; i < KT*(DK/4); i += 256) {
            int r = i >> 4, c4 = i & 15;
            float4 v = *(const float4*)(Kb + (size_t)(kc + r)*DK + c4*4);
            *(float4*)(kv + r*KSTR + c4*4) = v;
        }
        __syncthreads();
        #pragma unroll
        for (int j = 0; j < 8; j++) {
            int k = tk + j*16;
            const float* kp = kv + k*KSTR;
            float s = 0.f;
            #pragma unroll
            for (int c = 0; c < 16; c++) {
                float4 kvv = *(const float4*)(kp + c*4);
                s += qr[c].x*kvv.x + qr[c].y*kvv.y + qr[c].z*kvv.z + qr[c].w*kvv.w;
            }
            int kg = kc + k;
            sc[tq*SEQ + kg] = (msk[kg] == 0) ? -1e9f : s;
        }
        __syncthreads();
    }

    // ---- softmax over each of the QT rows (16 threads per row) ----
    float m = -3.0e38f;
    for (int k = tk; k < SEQ; k += 16) m = fmaxf(m, sc[tq*SEQ + k]);
    #pragma unroll
    for (int o = 8; o > 0; o >>= 1) m = fmaxf(m, __shfl_xor_sync(0xffffffffu, m, o, 16));
    float sum = 0.f;
    for (int k = tk; k < SEQ; k += 16) {
        float e = __expf(sc[tq*SEQ + k] - m);
        sc[tq*SEQ + k] = e;
        sum += e;
    }
    #pragma unroll
    for (int o = 8; o > 0; o >>= 1) sum += __shfl_xor_sync(0xffffffffu, sum, o, 16);
    if (tk == 0) rinv[tq] = 1.0f / sum;
    __syncthreads();

    // ---- write normalized att (coalesced float4) ----
    if (attout) {
        float* ab = attout + ((size_t)bh*SEQ + q0)*SEQ;
        for (int i = tid*4; i < QT*SEQ; i += 1024) {
            int r = i >> 11;
            float iv = rinv[r];
            float4 e = *(const float4*)(sc + i);
            e.x *= iv; e.y *= iv; e.z *= iv; e.w *= iv;
            *(float4*)(ab + i) = e;   // global row stride == SEQ == sc stride
        }
    }

    // ---- PV: ctx[tq][:] = (att row) @ V ----
    float4 cacc = make_float4(0.f, 0.f, 0.f, 0.f);
    for (int kc = 0; kc < SEQ; kc += KT) {
        __syncthreads();  // protect kv reuse
        for (int i = tid; i < KT*(DK/4); i += 256) {
            int r = i >> 4, c4 = i & 15;
            float4 v = *(const float4*)(Vb + (size_t)(kc + r)*DK + c4*4);
            *(float4*)(kv + r*KSTR + c4*4) = v;
        }
        __syncthreads();
        const float* srow = sc + tq*SEQ + kc;
        #pragma unroll 4
        for (int k = 0; k < KT; k++) {
            float a = srow[k];
            float4 vv = *(const float4*)(kv + k*KSTR + tk*4);
            cacc.x += a*vv.x; cacc.y += a*vv.y; cacc.z += a*vv.z; cacc.w += a*vv.w;
        }
    }
    float iv = rinv[tq];
    cacc.x *= iv; cacc.y *= iv; cacc.z *= iv; cacc.w *= iv;
    *(float4*)(ctx + (size_t)(b*SEQ + q0 + tq)*DMODEL + h*DK + tk*4) = cacc;
}

// ---------------- LayerNorm over last dim (1024), one CTA per row ----------------
__global__ __launch_bounds__(256) void ln_kernel(
    const float* __restrict__ pre, const float* __restrict__ gamma,
    const float* __restrict__ beta, float* __restrict__ out)
{
    const int tid = threadIdx.x;
    const int row = blockIdx.x;
    float4 v = ((const float4*)(pre + (size_t)row*DMODEL))[tid];
    float s  = v.x + v.y + v.z + v.w;
    float s2 = v.x*v.x + v.y*v.y + v.z*v.z + v.w*v.w;
    #pragma unroll
    for (int o = 16; o > 0; o >>= 1) {
        s  += __shfl_xor_sync(0xffffffffu, s,  o);
        s2 += __shfl_xor_sync(0xffffffffu, s2, o);
    }
    __shared__ float ws[8], ws2[8];
    __shared__ float mu_s, r_s;
    if ((tid & 31) == 0) { ws[tid >> 5] = s; ws2[tid >> 5] = s2; }
    __syncthreads();
    if (tid == 0) {
        float t = 0.f, t2 = 0.f;
        #pragma unroll
        for (int i = 0; i < 8; i++) { t += ws[i]; t2 += ws2[i]; }
        float mu  = t * (1.0f/DMODEL);
        float var = t2 * (1.0f/DMODEL) - mu*mu;
        mu_s = mu;
        r_s  = rsqrtf(var + 1e-5f);
    }
    __syncthreads();
    float mu = mu_s, r = r_s;
    float4 g  = ((const float4*)gamma)[tid];
    float4 be = ((const float4*)beta)[tid];
    float4 o;
    o.x = (v.x - mu)*r*g.x + be.x;
    o.y = (v.y - mu)*r*g.y + be.y;
    o.z = (v.z - mu)*r*g.z + be.z;
    o.w = (v.w - mu)*r*g.w + be.w;
    ((float4*)(out + (size_t)row*DMODEL))[tid] = o;
}

// ---------------- launch ----------------
extern "C" void kernel_launch(void* const* d_in, const int* in_sizes, int n_in,
                              void* d_out, int out_size)
{
    const float* x     = (const float*)d_in[0];
    const int*   mask  = (const int*)  d_in[1];
    const float* Wq    = (const float*)d_in[2];
    const float* bq    = (const float*)d_in[3];
    const float* Wk    = (const float*)d_in[4];
    const float* bk    = (const float*)d_in[5];
    const float* Wv    = (const float*)d_in[6];
    const float* bv    = (const float*)d_in[7];
    const float* Wo    = (const float*)d_in[8];
    const float* bo    = (const float*)d_in[9];
    const float* gamma = (const float*)d_in[10];
    const float* beta  = (const float*)d_in[11];
    float* out = (float*)d_out;

    void *pq, *pk, *pv, *pctx, *ppre;
    cudaGetSymbolAddress(&pq,   g_q);
    cudaGetSymbolAddress(&pk,   g_k);
    cudaGetSymbolAddress(&pv,   g_v);
    cudaGetSymbolAddress(&pctx, g_ctx);
    cudaGetSymbolAddress(&ppre, g_pre);

    const long long OUT_ELEMS = (long long)ROWS * DMODEL;                 // 8388608
    const long long ATT_ELEMS = (long long)BH * SEQ * SEQ;                // 268435456
    float* attout = ((long long)out_size >= OUT_ELEMS + ATT_ELEMS)
                        ? (out + OUT_ELEMS) : nullptr;

    cudaFuncSetAttribute(attn_kernel, cudaFuncAttributeMaxDynamicSharedMemorySize,
                         ATTN_SMEM_BYTES);

    dim3 gg(DMODEL/128, ROWS/128);
    gemm_kernel<<<gg, 256>>>(x, Wq, bq, nullptr, (float*)pq, 0, 0.125f);  // Q / sqrt(dk)
    gemm_kernel<<<gg, 256>>>(x, Wk, bk, nullptr, (float*)pk, 0, 1.0f);
    gemm_kernel<<<gg, 256>>>(x, Wv, bv, nullptr, (float*)pv, 0, 1.0f);

    attn_kernel<<<dim3(SEQ/QT, NHEADS, BATCH), 256, ATTN_SMEM_BYTES>>>(
        (const float*)pq, (const float*)pk, (const float*)pv, mask,
        (float*)pctx, attout);

    gemm_kernel<<<gg, 256>>>((const float*)pctx, Wo, bo, x, (float*)ppre, 1, 1.0f);
    ln_kernel<<<ROWS, 256>>>((const float*)ppre, gamma, beta, out);
}

// round 2
// speedup vs baseline: 1.1607x; 1.1607x over previous
#include <cuda_runtime.h>

#define DMODEL 1024
#define NHEADS 16
#define DK     64
#define BATCH  4
#define SEQ    2048
#define ROWS   (BATCH*SEQ)    // 8192
#define BH     (BATCH*NHEADS) // 64

// ---------------- scratch ----------------
__device__ float g_q[(size_t)BH*SEQ*DK];
__device__ float g_k[(size_t)BH*SEQ*DK];
__device__ float g_v[(size_t)BH*SEQ*DK];
__device__ float g_ctx[(size_t)ROWS*DMODEL];
__device__ float g_pre[(size_t)ROWS*DMODEL];

// ---------------- tf32 helpers ----------------
__device__ __forceinline__ unsigned f2tf(float f) {
    unsigned u; asm("cvt.rna.tf32.f32 %0, %1;" : "=r"(u) : "f"(f)); return u;
}
__device__ __forceinline__ void mma8(float* c, const unsigned* a, const unsigned* b) {
    asm volatile(
        "mma.sync.aligned.m16n8k8.row.col.f32.tf32.tf32.f32 "
        "{%0,%1,%2,%3}, {%4,%5,%6,%7}, {%8,%9}, {%0,%1,%2,%3};"
        : "+f"(c[0]), "+f"(c[1]), "+f"(c[2]), "+f"(c[3])
        : "r"(a[0]), "r"(a[1]), "r"(a[2]), "r"(a[3]), "r"(b[0]), "r"(b[1]));
}

// ---------------- tf32 GEMM: C = A(ROWSx1024) @ W(1024x1024) + bias ----------------
// Split-A (hi+lo tf32 planes), single-tf32 W.
// mode 0: scatter to per-head layout, scale; mode 1: +resid, row-major.
#define ASTR 36
#define BSTR 136
#define GEMM_SMEM ((128*ASTR*2 + 32*BSTR)*4)

__global__ __launch_bounds__(256) void gemm_tc(
    const float* __restrict__ A, const float* __restrict__ W,
    const float* __restrict__ bias, const float* __restrict__ resid,
    float* __restrict__ out, int mode, float scale)
{
    extern __shared__ unsigned gsm[];
    unsigned* Ah = gsm;                    // [128][ASTR]
    unsigned* Al = Ah + 128*ASTR;          // [128][ASTR]
    unsigned* Bs = Al + 128*ASTR;          // [32][BSTR]

    const int tid  = threadIdx.x;
    const int warp = tid >> 5, lane = tid & 31;
    const int g    = lane >> 2, t = lane & 3;
    const int wm   = warp >> 2, wn = warp & 3;   // 2 x 4 warp grid
    const int brow = blockIdx.y * 128;
    const int bcol = blockIdx.x * 128;

    float c[4][4][4];
    #pragma unroll
    for (int mt = 0; mt < 4; mt++)
        #pragma unroll
        for (int nt = 0; nt < 4; nt++)
            #pragma unroll
            for (int i = 0; i < 4; i++) c[mt][nt][i] = 0.f;

    for (int kt = 0; kt < DMODEL; kt += 32) {
        #pragma unroll
        for (int j = 0; j < 4; j++) {               // A tile 128x32
            int f = tid + 256*j;
            int r = f >> 3, c4 = (f & 7) * 4;
            float4 v = *(const float4*)(A + (size_t)(brow + r)*DMODEL + kt + c4);
            float vv[4] = {v.x, v.y, v.z, v.w};
            #pragma unroll
            for (int e = 0; e < 4; e++) {
                unsigned h = f2tf(vv[e]);
                Ah[r*ASTR + c4 + e] = h;
                Al[r*ASTR + c4 + e] = f2tf(vv[e] - __uint_as_float(h));
            }
        }
        #pragma unroll
        for (int j = 0; j < 4; j++) {               // W tile 32x128
            int f = tid + 256*j;
            int r = f >> 5, c4 = (f & 31) * 4;
            float4 v = *(const float4*)(W + (size_t)(kt + r)*DMODEL + bcol + c4);
            Bs[r*BSTR + c4 + 0] = f2tf(v.x);
            Bs[r*BSTR + c4 + 1] = f2tf(v.y);
            Bs[r*BSTR + c4 + 2] = f2tf(v.z);
            Bs[r*BSTR + c4 + 3] = f2tf(v.w);
        }
        __syncthreads();

        #pragma unroll
        for (int ks = 0; ks < 4; ks++) {
            unsigned bf[4][2];
            #pragma unroll
            for (int nt = 0; nt < 4; nt++) {
                int col = wn*32 + nt*8 + g;
                bf[nt][0] = Bs[(ks*8 + t    )*BSTR + col];
                bf[nt][1] = Bs[(ks*8 + t + 4)*BSTR + col];
            }
            #pragma unroll
            for (int mt = 0; mt < 4; mt++) {
                int r0 = wm*64 + mt*16 + g;
                int k0 = ks*8 + t;
                unsigned ah[4] = {Ah[r0*ASTR + k0], Ah[(r0+8)*ASTR + k0],
                                  Ah[r0*ASTR + k0+4], Ah[(r0+8)*ASTR + k0+4]};
                unsigned al[4] = {Al[r0*ASTR + k0], Al[(r0+8)*ASTR + k0],
                                  Al[r0*ASTR + k0+4], Al[(r0+8)*ASTR + k0+4]};
                #pragma unroll
                for (int nt = 0; nt < 4; nt++) {
                    mma8(c[mt][nt], ah, bf[nt]);
                    mma8(c[mt][nt], al, bf[nt]);
                }
            }
        }
        __syncthreads();
    }

    #pragma unroll
    for (int mt = 0; mt < 4; mt++)
        #pragma unroll
        for (int nt = 0; nt < 4; nt++)
            #pragma unroll
            for (int i = 0; i < 4; i++) {
                int row = brow + wm*64 + mt*16 + g + ((i >> 1) ? 8 : 0);
                int col = bcol + wn*32 + nt*8 + 2*t + (i & 1);
                float v = c[mt][nt][i] + bias[col];
                if (mode == 0) {
                    v *= scale;
                    int b = row >> 11, s = row & (SEQ-1);
                    int h = col >> 6,  d = col & (DK-1);
                    out[(size_t)((b*NHEADS + h)*SEQ + s)*DK + d] = v;
                } else {
                    v += resid[(size_t)row*DMODEL + col];
                    out[(size_t)row*DMODEL + col] = v;
                }
            }
}

// ---------------- fused attention (tensor core) ----------------
#define QT    16
#define CH    128
#define SCSTR 2056
#define KSTR  68
#define RST   66
#define ATTN_SMEM ((QT*SCSTR + CH*KSTR + 2*QT*KSTR + 8*QT*RST + SEQ + 32)*4)

__global__ __launch_bounds__(256, 1) void attn_tc(
    const float* __restrict__ Q, const float* __restrict__ K, const float* __restrict__ V,
    const int* __restrict__ mask, float* __restrict__ ctx, float* __restrict__ attout)
{
    extern __shared__ float sm[];
    float*    sc   = sm;                             // [QT][SCSTR] exp scores (fp32)
    unsigned* kvs  = (unsigned*)(sc + QT*SCSTR);     // [CH][KSTR] K/V tf32
    unsigned* qh   = kvs + CH*KSTR;                  // [QT][KSTR]
    unsigned* ql   = qh + QT*KSTR;                   // [QT][KSTR]
    float*    red  = (float*)(ql + QT*KSTR);         // [8][QT][RST]
    float*    mskf = red + 8*QT*RST;                 // [SEQ]
    float*    srow = mskf + SEQ;                     // [16]
    float*    rinv = srow + 16;                      // [16]

    const int tid  = threadIdx.x;
    const int warp = tid >> 5, lane = tid & 31;
    const int g    = lane >> 2, t = lane & 3;
    const int b    = blockIdx.z, h = blockIdx.y;
    const int bh   = b*NHEADS + h;
    const int q0   = blockIdx.x * QT;
    const float* Qb = Q + (size_t)bh*SEQ*DK;
    const float* Kb = K + (size_t)bh*SEQ*DK;
    const float* Vb = V + (size_t)bh*SEQ*DK;

    // stage mask as float, Q as hi/lo tf32
    for (int i = tid; i < SEQ; i += 256) mskf[i] = mask[b*SEQ + i] ? 1.f : 0.f;
    for (int i = tid; i < QT*DK; i += 256) {
        int r = i >> 6, c = i & 63;
        float v = Qb[(size_t)(q0 + r)*DK + c];
        unsigned hb = f2tf(v);
        qh[r*KSTR + c] = hb;
        ql[r*KSTR + c] = f2tf(v - __uint_as_float(hb));
    }
    if (tid < 16) srow[tid] = 0.f;
    __syncthreads();

    // ---- QK^T + exp + mask, per-chunk; row-sum accumulation ----
    float rs0 = 0.f, rs1 = 0.f;
    for (int kc = 0; kc < SEQ; kc += CH) {
        for (int i = tid; i < CH*DK; i += 256) {
            int r = i >> 6, c = i & 63;
            kvs[r*KSTR + c] = f2tf(Kb[(size_t)(kc + r)*DK + c]);
        }
        __syncthreads();

        float cc[2][4];
        #pragma unroll
        for (int nt = 0; nt < 2; nt++)
            #pragma unroll
            for (int i = 0; i < 4; i++) cc[nt][i] = 0.f;

        #pragma unroll
        for (int ks = 0; ks < 8; ks++) {
            int d0 = ks*8;
            unsigned ah[4] = {qh[g*KSTR + d0 + t],     qh[(g+8)*KSTR + d0 + t],
                              qh[g*KSTR + d0 + t + 4], qh[(g+8)*KSTR + d0 + t + 4]};
            unsigned al[4] = {ql[g*KSTR + d0 + t],     ql[(g+8)*KSTR + d0 + t],
                              ql[g*KSTR + d0 + t + 4], ql[(g+8)*KSTR + d0 + t + 4]};
            #pragma unroll
            for (int nt = 0; nt < 2; nt++) {
                int kl = warp*16 + nt*8 + g;
                unsigned bf[2] = {kvs[kl*KSTR + d0 + t], kvs[kl*KSTR + d0 + t + 4]};
                mma8(cc[nt], ah, bf);
                mma8(cc[nt], al, bf);
            }
        }
        #pragma unroll
        for (int nt = 0; nt < 2; nt++)
            #pragma unroll
            for (int i = 0; i < 4; i++) {
                int key = kc + warp*16 + nt*8 + 2*t + (i & 1);
                int row = g + ((i >> 1) ? 8 : 0);
                float e = __expf(cc[nt][i]) * mskf[key];
                sc[row*SCSTR + key] = e;
                if (i >> 1) rs1 += e; else rs0 += e;
            }
        __syncthreads();
    }

    // reduce row sums (4 lanes per row-group share), then across warps
    rs0 += __shfl_xor_sync(0xffffffffu, rs0, 1);
    rs0 += __shfl_xor_sync(0xffffffffu, rs0, 2);
    rs1 += __shfl_xor_sync(0xffffffffu, rs1, 1);
    rs1 += __shfl_xor_sync(0xffffffffu, rs1, 2);
    if (t == 0) { atomicAdd(&srow[g], rs0); atomicAdd(&srow[g+8], rs1); }
    __syncthreads();
    if (tid < 16) rinv[tid] = 1.0f / srow[tid];
    __syncthreads();

    // ---- write normalized att ----
    if (attout) {
        for (int i = tid; i < QT*(SEQ/4); i += 256) {
            int r = i >> 9, c4 = (i & 511) * 4;
            float iv = rinv[r];
            float4 e = *(const float4*)(sc + r*SCSTR + c4);
            e.x *= iv; e.y *= iv; e.z *= iv; e.w *= iv;
            *(float4*)(attout + ((size_t)bh*SEQ + q0 + r)*SEQ + c4) = e;
        }
    }

    // ---- PV: ctx = att @ V (k split across warps within each chunk) ----
    float cv[8][4];
    #pragma unroll
    for (int nt = 0; nt < 8; nt++)
        #pragma unroll
        for (int i = 0; i < 4; i++) cv[nt][i] = 0.f;

    for (int kc = 0; kc < SEQ; kc += CH) {
        __syncthreads();
        for (int i = tid; i < CH*DK; i += 256) {
            int r = i >> 6, c = i & 63;
            kvs[r*KSTR + c] = f2tf(Vb[(size_t)(kc + r)*DK + c]);
        }
        __syncthreads();
        #pragma unroll
        for (int j = 0; j < 2; j++) {
            int kk = (warp*2 + j)*8;      // local key base for this warp's kstep
            unsigned af[4] = {
                f2tf(sc[g*SCSTR     + kc + kk + t]),
                f2tf(sc[(g+8)*SCSTR + kc + kk + t]),
                f2tf(sc[g*SCSTR     + kc + kk + t + 4]),
                f2tf(sc[(g+8)*SCSTR + kc + kk + t + 4])};
            #pragma unroll
            for (int nt = 0; nt < 8; nt++) {
                unsigned bf[2] = {kvs[(kk + t)*KSTR + nt*8 + g],
                                  kvs[(kk + t + 4)*KSTR + nt*8 + g]};
                mma8(cv[nt], af, bf);
            }
        }
    }

    // stash per-warp partials, reduce across warps, scale, write ctx
    #pragma unroll
    for (int nt = 0; nt < 8; nt++)
        #pragma unroll
        for (int i = 0; i < 4; i++) {
            int row = g + ((i >> 1) ? 8 : 0);
            int col = nt*8 + 2*t + (i & 1);
            red[(warp*QT + row)*RST + col] = cv[nt][i];
        }
    __syncthreads();
    for (int o = tid; o < QT*DK; o += 256) {
        int row = o >> 6, col = o & 63;
        float s = 0.f;
        #pragma unroll
        for (int w = 0; w < 8; w++) s += red[(w*QT + row)*RST + col];
        s *= rinv[row];
        ctx[(size_t)(b*SEQ + q0 + row)*DMODEL + h*DK + col] = s;
    }
}

// ---------------- LayerNorm ----------------
__global__ __launch_bounds__(256) void ln_kernel(
    const float* __restrict__ pre, const float* __restrict__ gamma,
    const float* __restrict__ beta, float* __restrict__ out)
{
    const int tid = threadIdx.x;
    const int row = blockIdx.x;
    float4 v = ((const float4*)(pre + (size_t)row*DMODEL))[tid];
    float s  = v.x + v.y + v.z + v.w;
    float s2 = v.x*v.x + v.y*v.y + v.z*v.z + v.w*v.w;
    #pragma unroll
    for (int o = 16; o > 0; o >>= 1) {
        s  += __shfl_xor_sync(0xffffffffu, s,  o);
        s2 += __shfl_xor_sync(0xffffffffu, s2, o);
    }
    __shared__ float ws[8], ws2[8];
    __shared__ float mu_s, r_s;
    if ((tid & 31) == 0) { ws[tid >> 5] = s; ws2[tid >> 5] = s2; }
    __syncthreads();
    if (tid == 0) {
        float tt = 0.f, t2 = 0.f;
        #pragma unroll
        for (int i = 0; i < 8; i++) { tt += ws[i]; t2 += ws2[i]; }
        float mu  = tt * (1.0f/DMODEL);
        float var = t2 * (1.0f/DMODEL) - mu*mu;
        mu_s = mu;
        r_s  = rsqrtf(var + 1e-5f);
    }
    __syncthreads();
    float mu = mu_s, r = r_s;
    float4 gm = ((const float4*)gamma)[tid];
    float4 be = ((const float4*)beta)[tid];
    float4 o;
    o.x = (v.x - mu)*r*gm.x + be.x;
    o.y = (v.y - mu)*r*gm.y + be.y;
    o.z = (v.z - mu)*r*gm.z + be.z;
    o.w = (v.w - mu)*r*gm.w + be.w;
    ((float4*)(out + (size_t)row*DMODEL))[tid] = o;
}

// ---------------- launch ----------------
extern "C" void kernel_launch(void* const* d_in, const int* in_sizes, int n_in,
                              void* d_out, int out_size)
{
    const float* x     = (const float*)d_in[0];
    const int*   mask  = (const int*)  d_in[1];
    const float* Wq    = (const float*)d_in[2];
    const float* bq    = (const float*)d_in[3];
    const float* Wk    = (const float*)d_in[4];
    const float* bk    = (const float*)d_in[5];
    const float* Wv    = (const float*)d_in[6];
    const float* bv    = (const float*)d_in[7];
    const float* Wo    = (const float*)d_in[8];
    const float* bo    = (const float*)d_in[9];
    const float* gamma = (const float*)d_in[10];
    const float* beta  = (const float*)d_in[11];
    float* out = (float*)d_out;

    void *pq, *pk, *pv, *pctx, *ppre;
    cudaGetSymbolAddress(&pq,   g_q);
    cudaGetSymbolAddress(&pk,   g_k);
    cudaGetSymbolAddress(&pv,   g_v);
    cudaGetSymbolAddress(&pctx, g_ctx);
    cudaGetSymbolAddress(&ppre, g_pre);

    const long long OUT_ELEMS = (long long)ROWS * DMODEL;
    const long long ATT_ELEMS = (long long)BH * SEQ * SEQ;
    float* attout = ((long long)out_size >= OUT_ELEMS + ATT_ELEMS)
                        ? (out + OUT_ELEMS) : nullptr;

    cudaFuncSetAttribute(gemm_tc, cudaFuncAttributeMaxDynamicSharedMemorySize, GEMM_SMEM);
    cudaFuncSetAttribute(attn_tc, cudaFuncAttributeMaxDynamicSharedMemorySize, ATTN_SMEM);

    dim3 gg(DMODEL/128, ROWS/128);
    gemm_tc<<<gg, 256, GEMM_SMEM>>>(x, Wq, bq, nullptr, (float*)pq, 0, 0.125f);
    gemm_tc<<<gg, 256, GEMM_SMEM>>>(x, Wk, bk, nullptr, (float*)pk, 0, 1.0f);
    gemm_tc<<<gg, 256, GEMM_SMEM>>>(x, Wv, bv, nullptr, (float*)pv, 0, 1.0f);

    attn_tc<<<dim3(SEQ/QT, NHEADS, BATCH), 256, ATTN_SMEM>>>(
        (const float*)pq, (const float*)pk, (const float*)pv, mask,
        (float*)pctx, attout);

    gemm_tc<<<gg, 256, GEMM_SMEM>>>((const float*)pctx, Wo, bo, x, (float*)ppre, 1, 1.0f);
    ln_kernel<<<ROWS, 256>>>((const float*)ppre, gamma, beta, out);
}

// round 3
// speedup vs baseline: 3.2983x; 2.8416x over previous
#include <cuda_runtime.h>

#define DMODEL 1024
#define NHEADS 16
#define DK     64
#define BATCH  4
#define SEQ    2048
#define ROWS   (BATCH*SEQ)    // 8192
#define BH     (BATCH*NHEADS) // 64

// ---------------- scratch ----------------
__device__ float g_q[(size_t)BH*SEQ*DK];
__device__ float g_k[(size_t)BH*SEQ*DK];
__device__ float g_v[(size_t)BH*SEQ*DK];
__device__ float g_ctx[(size_t)ROWS*DMODEL];
__device__ float g_pre[(size_t)ROWS*DMODEL];
__device__ float g_rp[(size_t)BH*SEQ*16];   // per-tile row-sum partials

// ---------------- tf32 helpers ----------------
__device__ __forceinline__ unsigned f2tf(float f) {
    unsigned u; asm("cvt.rna.tf32.f32 %0, %1;" : "=r"(u) : "f"(f)); return u;
}
__device__ __forceinline__ void mma8(float* c, const unsigned* a, const unsigned* b) {
    asm volatile(
        "mma.sync.aligned.m16n8k8.row.col.f32.tf32.tf32.f32 "
        "{%0,%1,%2,%3}, {%4,%5,%6,%7}, {%8,%9}, {%0,%1,%2,%3};"
        : "+f"(c[0]), "+f"(c[1]), "+f"(c[2]), "+f"(c[3])
        : "r"(a[0]), "r"(a[1]), "r"(a[2]), "r"(a[3]), "r"(b[0]), "r"(b[1]));
}

// ---------------- tf32 GEMM: C = A(ROWSx1024) @ W(1024x1024) + bias ----------------
#define ASTR 36
#define BSTR 136
#define GEMM_SMEM ((128*ASTR*2 + 32*BSTR)*4)

__global__ __launch_bounds__(256) void gemm_tc(
    const float* __restrict__ A, const float* __restrict__ W,
    const float* __restrict__ bias, const float* __restrict__ resid,
    float* __restrict__ out, int mode, float scale)
{
    extern __shared__ unsigned gsm[];
    unsigned* Ah = gsm;
    unsigned* Al = Ah + 128*ASTR;
    unsigned* Bs = Al + 128*ASTR;

    const int tid  = threadIdx.x;
    const int warp = tid >> 5, lane = tid & 31;
    const int g    = lane >> 2, t = lane & 3;
    const int wm   = warp >> 2, wn = warp & 3;
    const int brow = blockIdx.y * 128;
    const int bcol = blockIdx.x * 128;

    float c[4][4][4];
    #pragma unroll
    for (int mt = 0; mt < 4; mt++)
        #pragma unroll
        for (int nt = 0; nt < 4; nt++)
            #pragma unroll
            for (int i = 0; i < 4; i++) c[mt][nt][i] = 0.f;

    for (int kt = 0; kt < DMODEL; kt += 32) {
        #pragma unroll
        for (int j = 0; j < 4; j++) {
            int f = tid + 256*j;
            int r = f >> 3, c4 = (f & 7) * 4;
            float4 v = *(const float4*)(A + (size_t)(brow + r)*DMODEL + kt + c4);
            float vv[4] = {v.x, v.y, v.z, v.w};
            #pragma unroll
            for (int e = 0; e < 4; e++) {
                unsigned hb = f2tf(vv[e]);
                Ah[r*ASTR + c4 + e] = hb;
                Al[r*ASTR + c4 + e] = f2tf(vv[e] - __uint_as_float(hb));
            }
        }
        #pragma unroll
        for (int j = 0; j < 4; j++) {
            int f = tid + 256*j;
            int r = f >> 5, c4 = (f & 31) * 4;
            float4 v = *(const float4*)(W + (size_t)(kt + r)*DMODEL + bcol + c4);
            Bs[r*BSTR + c4 + 0] = f2tf(v.x);
            Bs[r*BSTR + c4 + 1] = f2tf(v.y);
            Bs[r*BSTR + c4 + 2] = f2tf(v.z);
            Bs[r*BSTR + c4 + 3] = f2tf(v.w);
        }
        __syncthreads();

        #pragma unroll
        for (int ks = 0; ks < 4; ks++) {
            unsigned bf[4][2];
            #pragma unroll
            for (int nt = 0; nt < 4; nt++) {
                int col = wn*32 + nt*8 + g;
                bf[nt][0] = Bs[(ks*8 + t    )*BSTR + col];
                bf[nt][1] = Bs[(ks*8 + t + 4)*BSTR + col];
            }
            #pragma unroll
            for (int mt = 0; mt < 4; mt++) {
                int r0 = wm*64 + mt*16 + g;
                int k0 = ks*8 + t;
                unsigned ah[4] = {Ah[r0*ASTR + k0], Ah[(r0+8)*ASTR + k0],
                                  Ah[r0*ASTR + k0+4], Ah[(r0+8)*ASTR + k0+4]};
                unsigned al[4] = {Al[r0*ASTR + k0], Al[(r0+8)*ASTR + k0],
                                  Al[r0*ASTR + k0+4], Al[(r0+8)*ASTR + k0+4]};
                #pragma unroll
                for (int nt = 0; nt < 4; nt++) {
                    mma8(c[mt][nt], ah, bf[nt]);
                    mma8(c[mt][nt], al, bf[nt]);
                }
            }
        }
        __syncthreads();
    }

    #pragma unroll
    for (int mt = 0; mt < 4; mt++)
        #pragma unroll
        for (int nt = 0; nt < 4; nt++)
            #pragma unroll
            for (int i = 0; i < 4; i++) {
                int row = brow + wm*64 + mt*16 + g + ((i >> 1) ? 8 : 0);
                int col = bcol + wn*32 + nt*8 + 2*t + (i & 1);
                float v = c[mt][nt][i] + bias[col];
                if (mode == 0) {
                    v *= scale;
                    int b = row >> 11, s = row & (SEQ-1);
                    int h = col >> 6,  d = col & (DK-1);
                    out[(size_t)((b*NHEADS + h)*SEQ + s)*DK + d] = v;
                } else {
                    v += resid[(size_t)row*DMODEL + col];
                    out[(size_t)row*DMODEL + col] = v;
                }
            }
}

// ---------------- pass A: E = exp(QK^T) * mask (unnormalized), row-sum partials ----------------
#define ESTR 68
#define AQK_SMEM ((3*128*ESTR + 4*128 + 128)*4)

__global__ __launch_bounds__(256, 2) void attn_qk(
    const float* __restrict__ Q, const float* __restrict__ K,
    const int* __restrict__ mask, float* __restrict__ E, float* __restrict__ rpart)
{
    extern __shared__ unsigned sA[];
    unsigned* Qh = sA;                     // [128][ESTR]
    unsigned* Ql = Qh + 128*ESTR;
    unsigned* Ks = Ql + 128*ESTR;
    float* rsumw = (float*)(Ks + 128*ESTR); // [4][128]
    float* mskf  = rsumw + 4*128;           // [128]

    const int tid  = threadIdx.x;
    const int warp = tid >> 5, lane = tid & 31;
    const int g    = lane >> 2, t = lane & 3;
    const int wm   = warp >> 2, wn = warp & 3;
    const int n0   = blockIdx.x * 128;
    const int q0   = blockIdx.y * 128;
    const int bh   = blockIdx.z;
    const int b    = bh >> 4;
    const float* Qb = Q + (size_t)bh*SEQ*DK;
    const float* Kb = K + (size_t)bh*SEQ*DK;

    if (tid < 128) mskf[tid] = mask[b*SEQ + n0 + tid] ? 1.f : 0.f;

    #pragma unroll
    for (int j = 0; j < 8; j++) {          // Q tile 128x64 hi/lo
        int i = tid + 256*j;
        int r = i >> 4, c4 = (i & 15) * 4;
        float4 v = *(const float4*)(Qb + (size_t)(q0 + r)*DK + c4);
        float vv[4] = {v.x, v.y, v.z, v.w};
        #pragma unroll
        for (int e = 0; e < 4; e++) {
            unsigned hb = f2tf(vv[e]);
            Qh[r*ESTR + c4 + e] = hb;
            Ql[r*ESTR + c4 + e] = f2tf(vv[e] - __uint_as_float(hb));
        }
    }
    #pragma unroll
    for (int j = 0; j < 8; j++) {          // K tile 128x64
        int i = tid + 256*j;
        int r = i >> 4, c4 = (i & 15) * 4;
        float4 v = *(const float4*)(Kb + (size_t)(n0 + r)*DK + c4);
        Ks[r*ESTR + c4 + 0] = f2tf(v.x);
        Ks[r*ESTR + c4 + 1] = f2tf(v.y);
        Ks[r*ESTR + c4 + 2] = f2tf(v.z);
        Ks[r*ESTR + c4 + 3] = f2tf(v.w);
    }
    __syncthreads();

    float c[4][4][4];
    #pragma unroll
    for (int mt = 0; mt < 4; mt++)
        #pragma unroll
        for (int nt = 0; nt < 4; nt++)
            #pragma unroll
            for (int i = 0; i < 4; i++) c[mt][nt][i] = 0.f;

    #pragma unroll
    for (int ks = 0; ks < 8; ks++) {
        int k0 = ks*8;
        unsigned bf[4][2];
        #pragma unroll
        for (int nt = 0; nt < 4; nt++) {
            int col = wn*32 + nt*8 + g;
            bf[nt][0] = Ks[col*ESTR + k0 + t];
            bf[nt][1] = Ks[col*ESTR + k0 + t + 4];
        }
        #pragma unroll
        for (int mt = 0; mt < 4; mt++) {
            int r0 = wm*64 + mt*16 + g;
            unsigned ah[4] = {Qh[r0*ESTR + k0 + t], Qh[(r0+8)*ESTR + k0 + t],
                              Qh[r0*ESTR + k0 + t + 4], Qh[(r0+8)*ESTR + k0 + t + 4]};
            unsigned al[4] = {Ql[r0*ESTR + k0 + t], Ql[(r0+8)*ESTR + k0 + t],
                              Ql[r0*ESTR + k0 + t + 4], Ql[(r0+8)*ESTR + k0 + t + 4]};
            #pragma unroll
            for (int nt = 0; nt < 4; nt++) {
                mma8(c[mt][nt], ah, bf[nt]);
                mma8(c[mt][nt], al, bf[nt]);
            }
        }
    }

    // epilogue: exp*mask, write unnormalized E, accumulate row partial sums
    float ps[4][2];
    #pragma unroll
    for (int mt = 0; mt < 4; mt++) { ps[mt][0] = 0.f; ps[mt][1] = 0.f; }

    float* Eb = E + ((size_t)bh*SEQ + q0)*SEQ + n0;
    #pragma unroll
    for (int mt = 0; mt < 4; mt++)
        #pragma unroll
        for (int nt = 0; nt < 4; nt++)
            #pragma unroll
            for (int half = 0; half < 2; half++) {
                int row = wm*64 + mt*16 + g + half*8;
                int col = wn*32 + nt*8 + 2*t;
                float e0 = __expf(c[mt][nt][half*2 + 0]) * mskf[col];
                float e1 = __expf(c[mt][nt][half*2 + 1]) * mskf[col + 1];
                float2 ev = make_float2(e0, e1);
                *(float2*)(Eb + (size_t)row*SEQ + col) = ev;
                ps[mt][half] += e0 + e1;
            }
    #pragma unroll
    for (int mt = 0; mt < 4; mt++)
        #pragma unroll
        for (int half = 0; half < 2; half++) {
            float v = ps[mt][half];
            v += __shfl_xor_sync(0xffffffffu, v, 1);
            v += __shfl_xor_sync(0xffffffffu, v, 2);
            ps[mt][half] = v;
        }
    if (t == 0) {
        #pragma unroll
        for (int mt = 0; mt < 4; mt++)
            #pragma unroll
            for (int half = 0; half < 2; half++)
                rsumw[wn*128 + wm*64 + mt*16 + g + half*8] = ps[mt][half];
    }
    __syncthreads();
    if (tid < 128) {
        float s = rsumw[tid] + rsumw[128 + tid] + rsumw[256 + tid] + rsumw[384 + tid];
        rpart[((size_t)bh*SEQ + q0 + tid)*16 + blockIdx.x] = s;
    }
}

// ---------------- pass B: normalize att in place + ctx = att @ V ----------------
#define APV_SMEM ((128*ESTR + 64*ESTR + 128)*4)

__global__ __launch_bounds__(256) void attn_pv(
    const float* __restrict__ V, float* __restrict__ E,
    const float* __restrict__ rpart, float* __restrict__ ctx)
{
    extern __shared__ unsigned sB[];
    unsigned* Etf = sB;                    // [128][ESTR]
    unsigned* Vs  = Etf + 128*ESTR;        // [64][ESTR]
    float*    rinv = (float*)(Vs + 64*ESTR); // [128]

    const int tid  = threadIdx.x;
    const int warp = tid >> 5, lane = tid & 31;
    const int g    = lane >> 2, t = lane & 3;
    const int wm   = warp >> 2, wn = warp & 3;
    const int q0   = blockIdx.x * 128;
    const int bh   = blockIdx.y;
    const int b    = bh >> 4, h = bh & 15;
    const float* Vb = V + (size_t)bh*SEQ*DK;
    float* Eb = E + ((size_t)bh*SEQ + q0)*SEQ;

    if (tid < 128) {
        const float* rp = rpart + ((size_t)bh*SEQ + q0 + tid)*16;
        float s = 0.f;
        #pragma unroll
        for (int i = 0; i < 16; i++) s += rp[i];
        rinv[tid] = 1.0f / s;
    }
    __syncthreads();

    float c[4][2][4];
    #pragma unroll
    for (int mt = 0; mt < 4; mt++)
        #pragma unroll
        for (int nt = 0; nt < 2; nt++)
            #pragma unroll
            for (int i = 0; i < 4; i++) c[mt][nt][i] = 0.f;

    for (int kc = 0; kc < SEQ; kc += 64) {
        #pragma unroll
        for (int j = 0; j < 8; j++) {      // E chunk 128x64: normalize + write back + stage
            int i = tid + 256*j;
            int r = i >> 4, c4 = (i & 15) * 4;
            float* ep = Eb + (size_t)r*SEQ + kc + c4;
            float4 v = *(const float4*)ep;
            float iv = rinv[r];
            v.x *= iv; v.y *= iv; v.z *= iv; v.w *= iv;
            *(float4*)ep = v;
            Etf[r*ESTR + c4 + 0] = f2tf(v.x);
            Etf[r*ESTR + c4 + 1] = f2tf(v.y);
            Etf[r*ESTR + c4 + 2] = f2tf(v.z);
            Etf[r*ESTR + c4 + 3] = f2tf(v.w);
        }
        #pragma unroll
        for (int j = 0; j < 4; j++) {      // V chunk 64x64
            int i = tid + 256*j;
            int r = i >> 4, c4 = (i & 15) * 4;
            float4 v = *(const float4*)(Vb + (size_t)(kc + r)*DK + c4);
            Vs[r*ESTR + c4 + 0] = f2tf(v.x);
            Vs[r*ESTR + c4 + 1] = f2tf(v.y);
            Vs[r*ESTR + c4 + 2] = f2tf(v.z);
            Vs[r*ESTR + c4 + 3] = f2tf(v.w);
        }
        __syncthreads();

        #pragma unroll
        for (int ks = 0; ks < 8; ks++) {
            int k0 = ks*8;
            unsigned bf[2][2];
            #pragma unroll
            for (int nt = 0; nt < 2; nt++) {
                int col = wn*16 + nt*8 + g;
                bf[nt][0] = Vs[(k0 + t)*ESTR + col];
                bf[nt][1] = Vs[(k0 + t + 4)*ESTR + col];
            }
            #pragma unroll
            for (int mt = 0; mt < 4; mt++) {
                int r0 = wm*64 + mt*16 + g;
                unsigned af[4] = {Etf[r0*ESTR + k0 + t], Etf[(r0+8)*ESTR + k0 + t],
                                  Etf[r0*ESTR + k0 + t + 4], Etf[(r0+8)*ESTR + k0 + t + 4]};
                #pragma unroll
                for (int nt = 0; nt < 2; nt++) mma8(c[mt][nt], af, bf[nt]);
            }
        }
        __syncthreads();
    }

    #pragma unroll
    for (int mt = 0; mt < 4; mt++)
        #pragma unroll
        for (int nt = 0; nt < 2; nt++)
            #pragma unroll
            for (int half = 0; half < 2; half++) {
                int row = wm*64 + mt*16 + g + half*8;
                int col = wn*16 + nt*8 + 2*t;
                float2 ov = make_float2(c[mt][nt][half*2 + 0], c[mt][nt][half*2 + 1]);
                *(float2*)(ctx + (size_t)(b*SEQ + q0 + row)*DMODEL + h*DK + col) = ov;
            }
}

// ---------------- LayerNorm ----------------
__global__ __launch_bounds__(256) void ln_kernel(
    const float* __restrict__ pre, const float* __restrict__ gamma,
    const float* __restrict__ beta, float* __restrict__ out)
{
    const int tid = threadIdx.x;
    const int row = blockIdx.x;
    float4 v = ((const float4*)(pre + (size_t)row*DMODEL))[tid];
    float s  = v.x + v.y + v.z + v.w;
    float s2 = v.x*v.x + v.y*v.y + v.z*v.z + v.w*v.w;
    #pragma unroll
    for (int o = 16; o > 0; o >>= 1) {
        s  += __shfl_xor_sync(0xffffffffu, s,  o);
        s2 += __shfl_xor_sync(0xffffffffu, s2, o);
    }
    __shared__ float ws[8], ws2[8];
    __shared__ float mu_s, r_s;
    if ((tid & 31) == 0) { ws[tid >> 5] = s; ws2[tid >> 5] = s2; }
    __syncthreads();
    if (tid == 0) {
        float tt = 0.f, t2 = 0.f;
        #pragma unroll
        for (int i = 0; i < 8; i++) { tt += ws[i]; t2 += ws2[i]; }
        float mu  = tt * (1.0f/DMODEL);
        float var = t2 * (1.0f/DMODEL) - mu*mu;
        mu_s = mu;
        r_s  = rsqrtf(var + 1e-5f);
    }
    __syncthreads();
    float mu = mu_s, r = r_s;
    float4 gm = ((const float4*)gamma)[tid];
    float4 be = ((const float4*)beta)[tid];
    float4 o;
    o.x = (v.x - mu)*r*gm.x + be.x;
    o.y = (v.y - mu)*r*gm.y + be.y;
    o.z = (v.z - mu)*r*gm.z + be.z;
    o.w = (v.w - mu)*r*gm.w + be.w;
    ((float4*)(out + (size_t)row*DMODEL))[tid] = o;
}

// ---------------- launch ----------------
extern "C" void kernel_launch(void* const* d_in, const int* in_sizes, int n_in,
                              void* d_out, int out_size)
{
    const float* x     = (const float*)d_in[0];
    const int*   mask  = (const int*)  d_in[1];
    const float* Wq    = (const float*)d_in[2];
    const float* bq    = (const float*)d_in[3];
    const float* Wk    = (const float*)d_in[4];
    const float* bk    = (const float*)d_in[5];
    const float* Wv    = (const float*)d_in[6];
    const float* bv    = (const float*)d_in[7];
    const float* Wo    = (const float*)d_in[8];
    const float* bo    = (const float*)d_in[9];
    const float* gamma = (const float*)d_in[10];
    const float* beta  = (const float*)d_in[11];
    float* out = (float*)d_out;

    void *pq, *pk, *pv, *pctx, *ppre, *prp;
    cudaGetSymbolAddress(&pq,   g_q);
    cudaGetSymbolAddress(&pk,   g_k);
    cudaGetSymbolAddress(&pv,   g_v);
    cudaGetSymbolAddress(&pctx, g_ctx);
    cudaGetSymbolAddress(&ppre, g_pre);
    cudaGetSymbolAddress(&prp,  g_rp);

    const long long OUT_ELEMS = (long long)ROWS * DMODEL;
    float* attout = out + OUT_ELEMS;   // verified by R1/R2: out = [out | att]

    cudaFuncSetAttribute(gemm_tc, cudaFuncAttributeMaxDynamicSharedMemorySize, GEMM_SMEM);
    cudaFuncSetAttribute(attn_qk, cudaFuncAttributeMaxDynamicSharedMemorySize, AQK_SMEM);
    cudaFuncSetAttribute(attn_pv, cudaFuncAttributeMaxDynamicSharedMemorySize, APV_SMEM);

    dim3 gg(DMODEL/128, ROWS/128);
    gemm_tc<<<gg, 256, GEMM_SMEM>>>(x, Wq, bq, nullptr, (float*)pq, 0, 0.125f);
    gemm_tc<<<gg, 256, GEMM_SMEM>>>(x, Wk, bk, nullptr, (float*)pk, 0, 1.0f);
    gemm_tc<<<gg, 256, GEMM_SMEM>>>(x, Wv, bv, nullptr, (float*)pv, 0, 1.0f);

    attn_qk<<<dim3(SEQ/128, SEQ/128, BH), 256, AQK_SMEM>>>(
        (const float*)pq, (const float*)pk, mask, attout, (float*)prp);
    attn_pv<<<dim3(SEQ/128, BH), 256, APV_SMEM>>>(
        (const float*)pv, attout, (const float*)prp, (float*)pctx);

    gemm_tc<<<gg, 256, GEMM_SMEM>>>((const float*)pctx, Wo, bo, x, (float*)ppre, 1, 1.0f);
    ln_kernel<<<ROWS, 256>>>((const float*)ppre, gamma, beta, out);
}

// round 4
// speedup vs baseline: 5.3939x; 1.6354x over previous
#include <cuda_runtime.h>

#define DMODEL 1024
#define NHEADS 16
#define DK     64
#define BATCH  4
#define SEQ    2048
#define ROWS   (BATCH*SEQ)    // 8192
#define BH     (BATCH*NHEADS) // 64

// ---------------- scratch ----------------
__device__ float g_q[(size_t)BH*SEQ*DK];
__device__ float g_k[(size_t)BH*SEQ*DK];
__device__ float g_v[(size_t)BH*SEQ*DK];
__device__ float g_ctx[(size_t)ROWS*DMODEL];
__device__ float g_pre[(size_t)ROWS*DMODEL];
__device__ float g_rinv[(size_t)BH*SEQ];

// ---------------- tf32 helpers ----------------
__device__ __forceinline__ unsigned f2tf(float f) {
    unsigned u; asm("cvt.rna.tf32.f32 %0, %1;" : "=r"(u) : "f"(f)); return u;
}
__device__ __forceinline__ void mma8(float* c, const unsigned* a, const unsigned* b) {
    asm volatile(
        "mma.sync.aligned.m16n8k8.row.col.f32.tf32.tf32.f32 "
        "{%0,%1,%2,%3}, {%4,%5,%6,%7}, {%8,%9}, {%0,%1,%2,%3};"
        : "+f"(c[0]), "+f"(c[1]), "+f"(c[2]), "+f"(c[3])
        : "r"(a[0]), "r"(a[1]), "r"(a[2]), "r"(a[3]), "r"(b[0]), "r"(b[1]));
}

// ---------------- tf32 GEMM (single precision plane) ----------------
#define ASTR 36
#define BSTR 136
#define GEMM_SMEM ((128*ASTR + 32*BSTR)*4)

__global__ __launch_bounds__(256) void gemm_tc(
    const float* __restrict__ A, const float* __restrict__ W,
    const float* __restrict__ bias, const float* __restrict__ resid,
    float* __restrict__ out, int mode, float scale)
{
    extern __shared__ unsigned gsm[];
    unsigned* As = gsm;                 // [128][ASTR]
    unsigned* Bs = As + 128*ASTR;       // [32][BSTR]

    const int tid  = threadIdx.x;
    const int warp = tid >> 5, lane = tid & 31;
    const int g    = lane >> 2, t = lane & 3;
    const int wm   = warp >> 2, wn = warp & 3;
    const int brow = blockIdx.y * 128;
    const int bcol = blockIdx.x * 128;

    float c[4][4][4];
    #pragma unroll
    for (int mt = 0; mt < 4; mt++)
        #pragma unroll
        for (int nt = 0; nt < 4; nt++)
            #pragma unroll
            for (int i = 0; i < 4; i++) c[mt][nt][i] = 0.f;

    for (int kt = 0; kt < DMODEL; kt += 32) {
        #pragma unroll
        for (int j = 0; j < 4; j++) {
            int f = tid + 256*j;
            int r = f >> 3, c4 = (f & 7) * 4;
            float4 v = *(const float4*)(A + (size_t)(brow + r)*DMODEL + kt + c4);
            As[r*ASTR + c4 + 0] = f2tf(v.x);
            As[r*ASTR + c4 + 1] = f2tf(v.y);
            As[r*ASTR + c4 + 2] = f2tf(v.z);
            As[r*ASTR + c4 + 3] = f2tf(v.w);
        }
        #pragma unroll
        for (int j = 0; j < 4; j++) {
            int f = tid + 256*j;
            int r = f >> 5, c4 = (f & 31) * 4;
            float4 v = *(const float4*)(W + (size_t)(kt + r)*DMODEL + bcol + c4);
            Bs[r*BSTR + c4 + 0] = f2tf(v.x);
            Bs[r*BSTR + c4 + 1] = f2tf(v.y);
            Bs[r*BSTR + c4 + 2] = f2tf(v.z);
            Bs[r*BSTR + c4 + 3] = f2tf(v.w);
        }
        __syncthreads();

        #pragma unroll
        for (int ks = 0; ks < 4; ks++) {
            unsigned bf[4][2];
            #pragma unroll
            for (int nt = 0; nt < 4; nt++) {
                int col = wn*32 + nt*8 + g;
                bf[nt][0] = Bs[(ks*8 + t    )*BSTR + col];
                bf[nt][1] = Bs[(ks*8 + t + 4)*BSTR + col];
            }
            #pragma unroll
            for (int mt = 0; mt < 4; mt++) {
                int r0 = wm*64 + mt*16 + g;
                int k0 = ks*8 + t;
                unsigned af[4] = {As[r0*ASTR + k0], As[(r0+8)*ASTR + k0],
                                  As[r0*ASTR + k0+4], As[(r0+8)*ASTR + k0+4]};
                #pragma unroll
                for (int nt = 0; nt < 4; nt++) mma8(c[mt][nt], af, bf[nt]);
            }
        }
        __syncthreads();
    }

    #pragma unroll
    for (int mt = 0; mt < 4; mt++)
        #pragma unroll
        for (int nt = 0; nt < 4; nt++)
            #pragma unroll
            for (int i = 0; i < 4; i++) {
                int row = brow + wm*64 + mt*16 + g + ((i >> 1) ? 8 : 0);
                int col = bcol + wn*32 + nt*8 + 2*t + (i & 1);
                float v = c[mt][nt][i] + bias[col];
                if (mode == 0) {
                    v *= scale;
                    int b = row >> 11, s = row & (SEQ-1);
                    int h = col >> 6,  d = col & (DK-1);
                    out[(size_t)((b*NHEADS + h)*SEQ + s)*DK + d] = v;
                } else {
                    v += resid[(size_t)row*DMODEL + col];
                    out[(size_t)row*DMODEL + col] = v;
                }
            }
}

// ---------------- pass A: row sums of exp(QK^T)*mask (no E store) ----------------
#define QSTR 68
#define SUM_SMEM ((128*QSTR + 128*QSTR + 128 + 4*128)*4)

__global__ __launch_bounds__(256, 2) void attn_sums(
    const float* __restrict__ Q, const float* __restrict__ K,
    const int* __restrict__ mask, float* __restrict__ rinvg)
{
    extern __shared__ unsigned sA[];
    unsigned* Qs = sA;                       // [128][QSTR]
    unsigned* Ks = Qs + 128*QSTR;            // [128][QSTR]
    float* mskf  = (float*)(Ks + 128*QSTR);  // [128]
    float* red   = mskf + 128;               // [4][128]

    const int tid  = threadIdx.x;
    const int warp = tid >> 5, lane = tid & 31;
    const int g    = lane >> 2, t = lane & 3;
    const int wm   = warp >> 2, wn = warp & 3;
    const int q0   = blockIdx.x * 128;
    const int bh   = blockIdx.y;
    const int b    = bh >> 4;
    const float* Qb = Q + (size_t)bh*SEQ*DK;
    const float* Kb = K + (size_t)bh*SEQ*DK;

    #pragma unroll
    for (int j = 0; j < 8; j++) {
        int i = tid + 256*j;
        int r = i >> 4, c4 = (i & 15) * 4;
        float4 v = *(const float4*)(Qb + (size_t)(q0 + r)*DK + c4);
        Qs[r*QSTR + c4 + 0] = f2tf(v.x);
        Qs[r*QSTR + c4 + 1] = f2tf(v.y);
        Qs[r*QSTR + c4 + 2] = f2tf(v.z);
        Qs[r*QSTR + c4 + 3] = f2tf(v.w);
    }

    float ps[4][2];
    #pragma unroll
    for (int mt = 0; mt < 4; mt++) { ps[mt][0] = 0.f; ps[mt][1] = 0.f; }

    for (int kc = 0; kc < SEQ; kc += 128) {
        if (tid < 128) mskf[tid] = mask[b*SEQ + kc + tid] ? 1.f : 0.f;
        #pragma unroll
        for (int j = 0; j < 8; j++) {
            int i = tid + 256*j;
            int r = i >> 4, c4 = (i & 15) * 4;
            float4 v = *(const float4*)(Kb + (size_t)(kc + r)*DK + c4);
            Ks[r*QSTR + c4 + 0] = f2tf(v.x);
            Ks[r*QSTR + c4 + 1] = f2tf(v.y);
            Ks[r*QSTR + c4 + 2] = f2tf(v.z);
            Ks[r*QSTR + c4 + 3] = f2tf(v.w);
        }
        __syncthreads();

        float c[4][4][4];
        #pragma unroll
        for (int mt = 0; mt < 4; mt++)
            #pragma unroll
            for (int nt = 0; nt < 4; nt++)
                #pragma unroll
                for (int i = 0; i < 4; i++) c[mt][nt][i] = 0.f;

        #pragma unroll
        for (int ks = 0; ks < 8; ks++) {
            int k0 = ks*8;
            unsigned bf[4][2];
            #pragma unroll
            for (int nt = 0; nt < 4; nt++) {
                int col = wn*32 + nt*8 + g;
                bf[nt][0] = Ks[col*QSTR + k0 + t];
                bf[nt][1] = Ks[col*QSTR + k0 + t + 4];
            }
            #pragma unroll
            for (int mt = 0; mt < 4; mt++) {
                int r0 = wm*64 + mt*16 + g;
                unsigned af[4] = {Qs[r0*QSTR + k0 + t], Qs[(r0+8)*QSTR + k0 + t],
                                  Qs[r0*QSTR + k0 + t + 4], Qs[(r0+8)*QSTR + k0 + t + 4]};
                #pragma unroll
                for (int nt = 0; nt < 4; nt++) mma8(c[mt][nt], af, bf[nt]);
            }
        }
        #pragma unroll
        for (int mt = 0; mt < 4; mt++)
            #pragma unroll
            for (int nt = 0; nt < 4; nt++)
                #pragma unroll
                for (int half = 0; half < 2; half++) {
                    int col = wn*32 + nt*8 + 2*t;
                    ps[mt][half] += __expf(c[mt][nt][half*2 + 0]) * mskf[col]
                                  + __expf(c[mt][nt][half*2 + 1]) * mskf[col + 1];
                }
        __syncthreads();
    }

    #pragma unroll
    for (int mt = 0; mt < 4; mt++)
        #pragma unroll
        for (int half = 0; half < 2; half++) {
            float v = ps[mt][half];
            v += __shfl_xor_sync(0xffffffffu, v, 1);
            v += __shfl_xor_sync(0xffffffffu, v, 2);
            ps[mt][half] = v;
        }
    if (t == 0) {
        #pragma unroll
        for (int mt = 0; mt < 4; mt++)
            #pragma unroll
            for (int half = 0; half < 2; half++)
                red[wn*128 + wm*64 + mt*16 + g + half*8] = ps[mt][half];
    }
    __syncthreads();
    if (tid < 128) {
        float s = red[tid] + red[128 + tid] + red[256 + tid] + red[384 + tid];
        rinvg[(size_t)bh*SEQ + q0 + tid] = 1.0f / s;
    }
}

// ---------------- pass B: recompute QK, normalize, write att, PV in registers ----------------
#define VSTR 72
#define FUS_SMEM ((128*QSTR + 64*QSTR + 64*VSTR + 128*QSTR + 64 + 128 + 16)*4)

__global__ __launch_bounds__(256, 2) void attn_fused(
    const float* __restrict__ Q, const float* __restrict__ K, const float* __restrict__ V,
    const int* __restrict__ mask, const float* __restrict__ rinvg,
    float* __restrict__ ctx, float* __restrict__ attout)
{
    extern __shared__ unsigned sB[];
    unsigned* Qs = sB;                        // [128][QSTR] tf32
    unsigned* Ks = Qs + 128*QSTR;             // [64][QSTR] tf32
    unsigned* Vs = Ks + 64*QSTR;              // [64][VSTR] tf32
    float*    Es = (float*)(Vs + 64*VSTR);    // [128][QSTR] fp32 normalized exp
    float*    mskf = Es + 128*QSTR;           // [64]
    float*    rinv = mskf + 64;               // [128]

    const int tid  = threadIdx.x;
    const int warp = tid >> 5, lane = tid & 31;
    const int g    = lane >> 2, t = lane & 3;
    const int wm   = warp >> 1, wn = warp & 1;   // 4 x 2 warp grid (32x32 tiles)
    const int q0   = blockIdx.x * 128;
    const int bh   = blockIdx.y;
    const int b    = bh >> 4, h = bh & 15;
    const float* Qb = Q + (size_t)bh*SEQ*DK;
    const float* Kb = K + (size_t)bh*SEQ*DK;
    const float* Vb = V + (size_t)bh*SEQ*DK;

    if (tid < 128) rinv[tid] = rinvg[(size_t)bh*SEQ + q0 + tid];
    #pragma unroll
    for (int j = 0; j < 8; j++) {
        int i = tid + 256*j;
        int r = i >> 4, c4 = (i & 15) * 4;
        float4 v = *(const float4*)(Qb + (size_t)(q0 + r)*DK + c4);
        Qs[r*QSTR + c4 + 0] = f2tf(v.x);
        Qs[r*QSTR + c4 + 1] = f2tf(v.y);
        Qs[r*QSTR + c4 + 2] = f2tf(v.z);
        Qs[r*QSTR + c4 + 3] = f2tf(v.w);
    }

    float d[2][4][4];
    #pragma unroll
    for (int mt = 0; mt < 2; mt++)
        #pragma unroll
        for (int nt = 0; nt < 4; nt++)
            #pragma unroll
            for (int i = 0; i < 4; i++) d[mt][nt][i] = 0.f;

    for (int kc = 0; kc < SEQ; kc += 64) {
        if (tid < 64) mskf[tid] = mask[b*SEQ + kc + tid] ? 1.f : 0.f;
        #pragma unroll
        for (int j = 0; j < 4; j++) {          // K chunk 64x64
            int i = tid + 256*j;
            int r = i >> 4, c4 = (i & 15) * 4;
            float4 v = *(const float4*)(Kb + (size_t)(kc + r)*DK + c4);
            Ks[r*QSTR + c4 + 0] = f2tf(v.x);
            Ks[r*QSTR + c4 + 1] = f2tf(v.y);
            Ks[r*QSTR + c4 + 2] = f2tf(v.z);
            Ks[r*QSTR + c4 + 3] = f2tf(v.w);
        }
        #pragma unroll
        for (int j = 0; j < 4; j++) {          // V chunk 64x64
            int i = tid + 256*j;
            int r = i >> 4, c4 = (i & 15) * 4;
            float4 v = *(const float4*)(Vb + (size_t)(kc + r)*DK + c4);
            Vs[r*VSTR + c4 + 0] = f2tf(v.x);
            Vs[r*VSTR + c4 + 1] = f2tf(v.y);
            Vs[r*VSTR + c4 + 2] = f2tf(v.z);
            Vs[r*VSTR + c4 + 3] = f2tf(v.w);
        }
        __syncthreads();

        // ---- S = QK^T (identical mma chain to attn_sums) ----
        float c[2][4][4];
        #pragma unroll
        for (int mt = 0; mt < 2; mt++)
            #pragma unroll
            for (int nt = 0; nt < 4; nt++)
                #pragma unroll
                for (int i = 0; i < 4; i++) c[mt][nt][i] = 0.f;

        #pragma unroll
        for (int ks = 0; ks < 8; ks++) {
            int k0 = ks*8;
            unsigned bf[4][2];
            #pragma unroll
            for (int nt = 0; nt < 4; nt++) {
                int col = wn*32 + nt*8 + g;
                bf[nt][0] = Ks[col*QSTR + k0 + t];
                bf[nt][1] = Ks[col*QSTR + k0 + t + 4];
            }
            #pragma unroll
            for (int mt = 0; mt < 2; mt++) {
                int r0 = wm*32 + mt*16 + g;
                unsigned af[4] = {Qs[r0*QSTR + k0 + t], Qs[(r0+8)*QSTR + k0 + t],
                                  Qs[r0*QSTR + k0 + t + 4], Qs[(r0+8)*QSTR + k0 + t + 4]};
                #pragma unroll
                for (int nt = 0; nt < 4; nt++) mma8(c[mt][nt], af, bf[nt]);
            }
        }

        // ---- epilogue: normalized exp into Es ----
        #pragma unroll
        for (int mt = 0; mt < 2; mt++)
            #pragma unroll
            for (int nt = 0; nt < 4; nt++)
                #pragma unroll
                for (int half = 0; half < 2; half++) {
                    int row = wm*32 + mt*16 + g + half*8;
                    int col = wn*32 + nt*8 + 2*t;
                    float iv = rinv[row];
                    float e0 = __expf(c[mt][nt][half*2 + 0]) * mskf[col]     * iv;
                    float e1 = __expf(c[mt][nt][half*2 + 1]) * mskf[col + 1] * iv;
                    *(float2*)(Es + row*QSTR + col) = make_float2(e0, e1);
                }
        __syncthreads();

        // ---- write att chunk (coalesced float4) ----
        #pragma unroll
        for (int j = 0; j < 8; j++) {
            int i = tid + 256*j;
            int r = i >> 4, c4 = (i & 15) * 4;
            float4 v = *(const float4*)(Es + r*QSTR + c4);
            *(float4*)(attout + ((size_t)bh*SEQ + q0 + r)*SEQ + kc + c4) = v;
        }

        // ---- PV mma ----
        #pragma unroll
        for (int ks = 0; ks < 8; ks++) {
            int k0 = ks*8;
            unsigned bf[4][2];
            #pragma unroll
            for (int nt = 0; nt < 4; nt++) {
                int col = wn*32 + nt*8 + g;
                bf[nt][0] = Vs[(k0 + t)*VSTR + col];
                bf[nt][1] = Vs[(k0 + t + 4)*VSTR + col];
            }
            #pragma unroll
            for (int mt = 0; mt < 2; mt++) {
                int r0 = wm*32 + mt*16 + g;
                unsigned af[4] = {f2tf(Es[r0*QSTR + k0 + t]),
                                  f2tf(Es[(r0+8)*QSTR + k0 + t]),
                                  f2tf(Es[r0*QSTR + k0 + t + 4]),
                                  f2tf(Es[(r0+8)*QSTR + k0 + t + 4])};
                #pragma unroll
                for (int nt = 0; nt < 4; nt++) mma8(d[mt][nt], af, bf[nt]);
            }
        }
        __syncthreads();
    }

    #pragma unroll
    for (int mt = 0; mt < 2; mt++)
        #pragma unroll
        for (int nt = 0; nt < 4; nt++)
            #pragma unroll
            for (int half = 0; half < 2; half++) {
                int row = wm*32 + mt*16 + g + half*8;
                int col = wn*32 + nt*8 + 2*t;
                float2 ov = make_float2(d[mt][nt][half*2 + 0], d[mt][nt][half*2 + 1]);
                *(float2*)(ctx + (size_t)(b*SEQ + q0 + row)*DMODEL + h*DK + col) = ov;
            }
}

// ---------------- LayerNorm ----------------
__global__ __launch_bounds__(256) void ln_kernel(
    const float* __restrict__ pre, const float* __restrict__ gamma,
    const float* __restrict__ beta, float* __restrict__ out)
{
    const int tid = threadIdx.x;
    const int row = blockIdx.x;
    float4 v = ((const float4*)(pre + (size_t)row*DMODEL))[tid];
    float s  = v.x + v.y + v.z + v.w;
    float s2 = v.x*v.x + v.y*v.y + v.z*v.z + v.w*v.w;
    #pragma unroll
    for (int o = 16; o > 0; o >>= 1) {
        s  += __shfl_xor_sync(0xffffffffu, s,  o);
        s2 += __shfl_xor_sync(0xffffffffu, s2, o);
    }
    __shared__ float ws[8], ws2[8];
    __shared__ float mu_s, r_s;
    if ((tid & 31) == 0) { ws[tid >> 5] = s; ws2[tid >> 5] = s2; }
    __syncthreads();
    if (tid == 0) {
        float tt = 0.f, t2 = 0.f;
        #pragma unroll
        for (int i = 0; i < 8; i++) { tt += ws[i]; t2 += ws2[i]; }
        float mu  = tt * (1.0f/DMODEL);
        float var = t2 * (1.0f/DMODEL) - mu*mu;
        mu_s = mu;
        r_s  = rsqrtf(var + 1e-5f);
    }
    __syncthreads();
    float mu = mu_s, r = r_s;
    float4 gm = ((const float4*)gamma)[tid];
    float4 be = ((const float4*)beta)[tid];
    float4 o;
    o.x = (v.x - mu)*r*gm.x + be.x;
    o.y = (v.y - mu)*r*gm.y + be.y;
    o.z = (v.z - mu)*r*gm.z + be.z;
    o.w = (v.w - mu)*r*gm.w + be.w;
    ((float4*)(out + (size_t)row*DMODEL))[tid] = o;
}

// ---------------- launch ----------------
extern "C" void kernel_launch(void* const* d_in, const int* in_sizes, int n_in,
                              void* d_out, int out_size)
{
    const float* x     = (const float*)d_in[0];
    const int*   mask  = (const int*)  d_in[1];
    const float* Wq    = (const float*)d_in[2];
    const float* bq    = (const float*)d_in[3];
    const float* Wk    = (const float*)d_in[4];
    const float* bk    = (const float*)d_in[5];
    const float* Wv    = (const float*)d_in[6];
    const float* bv    = (const float*)d_in[7];
    const float* Wo    = (const float*)d_in[8];
    const float* bo    = (const float*)d_in[9];
    const float* gamma = (const float*)d_in[10];
    const float* beta  = (const float*)d_in[11];
    float* out = (float*)d_out;

    void *pq, *pk, *pv, *pctx, *ppre, *pri;
    cudaGetSymbolAddress(&pq,   g_q);
    cudaGetSymbolAddress(&pk,   g_k);
    cudaGetSymbolAddress(&pv,   g_v);
    cudaGetSymbolAddress(&pctx, g_ctx);
    cudaGetSymbolAddress(&ppre, g_pre);
    cudaGetSymbolAddress(&pri,  g_rinv);

    const long long OUT_ELEMS = (long long)ROWS * DMODEL;
    float* attout = out + OUT_ELEMS;

    cudaFuncSetAttribute(gemm_tc,    cudaFuncAttributeMaxDynamicSharedMemorySize, GEMM_SMEM);
    cudaFuncSetAttribute(attn_sums,  cudaFuncAttributeMaxDynamicSharedMemorySize, SUM_SMEM);
    cudaFuncSetAttribute(attn_fused, cudaFuncAttributeMaxDynamicSharedMemorySize, FUS_SMEM);

    dim3 gg(DMODEL/128, ROWS/128);
    gemm_tc<<<gg, 256, GEMM_SMEM>>>(x, Wq, bq, nullptr, (float*)pq, 0, 0.125f);
    gemm_tc<<<gg, 256, GEMM_SMEM>>>(x, Wk, bk, nullptr, (float*)pk, 0, 1.0f);
    gemm_tc<<<gg, 256, GEMM_SMEM>>>(x, Wv, bv, nullptr, (float*)pv, 0, 1.0f);

    attn_sums<<<dim3(SEQ/128, BH), 256, SUM_SMEM>>>(
        (const float*)pq, (const float*)pk, mask, (float*)pri);
    attn_fused<<<dim3(SEQ/128, BH), 256, FUS_SMEM>>>(
        (const float*)pq, (const float*)pk, (const float*)pv, mask,
        (const float*)pri, (float*)pctx, attout);

    gemm_tc<<<gg, 256, GEMM_SMEM>>>((const float*)pctx, Wo, bo, x, (float*)ppre, 1, 1.0f);
    ln_kernel<<<ROWS, 256>>>((const float*)ppre, gamma, beta, out);
}